// round 10
// baseline (speedup 1.0000x reference)
#include <cuda_runtime.h>

// Problem constants (fixed by setup_inputs): B=4, N=M=8192, D=3
constexpr int Bn = 4;
constexpr int Nn = 8192;
constexpr int Mn = 8192;
constexpr int BN = Bn * Nn;  // 32768 (= Bn*Mn too)

constexpr int TC    = 256;   // target chunk staged in shared
constexpr int R     = 8;     // source rows per thread
constexpr int T     = 128;   // threads per block
constexpr int ST    = T * R; // 1024 source rows per block
constexpr int NWARP = T / 32;
constexpr int NBX   = Mn / TC;  // 32 target chunks
constexpr int NBY   = Nn / ST;  // 8 source tiles
constexpr int NCS   = NBY * NWARP;  // 32 column-partial slices (per-warp)

// Partial-min scratch (written unconditionally every call -> no init needed)
__device__ float g_rowp[NBX * BN];   // [bx][b*Nn+row] : row min of d2 over chunk bx
__device__ float g_colp[NCS * BN];   // [by*4+w][b*Mn+col] : per-warp col min of d2
__device__ float g_bsum[256];        // per-block partial sums from reduce stage

// FFMA with immediate multiplier 1.0 -> rt=1 imm-form, not demotable to FADD
__device__ __forceinline__ float fma1(float a, float c) {
    float d; asm("fma.rn.f32 %0, %1, 0f3F800000, %2;" : "=f"(d) : "f"(a), "f"(c));
    return d;
}
// Bare warp min-reduce (REDUX)
__device__ __forceinline__ unsigned redux_min(unsigned v) {
    unsigned d;
    asm("redux.sync.min.u32 %0, %1, 0xffffffff;" : "=r"(d) : "r"(v));
    return d;
}
// 3-input integer min via the video instruction (fused VIMNMX on sm_90+).
// Raw fp32 bits of nonneg floats order identically under s32 compare.
__device__ __forceinline__ unsigned min3u(unsigned a, unsigned b, unsigned c) {
    int d;
    asm("vmin.s32.s32.s32.min %0, %1, %2, %3;"
        : "=r"(d) : "r"((int)a), "r"((int)b), "r"((int)c));
    return (unsigned)d;
}

__global__ __launch_bounds__(T, 7)   // 7*148 >= 1024 blocks: one wave
void chamfer_main(const float* __restrict__ src, const float* __restrict__ tgt) {
    __shared__ float4 tsh[TC];   // target x,y,z,|t|^2  (4KB)

    const int tid  = threadIdx.x;
    const int lane = tid & 31;
    const int w    = tid >> 5;
    const int bx   = blockIdx.x;
    const int by   = blockIdx.y;
    const int b    = blockIdx.z;
    const int s0   = by * ST;
    const int t0   = bx * TC;

    // Stage target chunk into shared (x, y, z, |t|^2)
    for (int i = tid; i < TC; i += T) {
        const float* p = tgt + ((size_t)b * Mn + t0 + i) * 3;
        float x = p[0], y = p[1], z = p[2];
        tsh[i] = make_float4(x, y, z, fmaf(x, x, fmaf(y, y, z * z)));
    }

    // Source rows: NEGATED-DOUBLED coords so the dot chain seeds with t.w
    float sxn[R], syn[R], szn[R], sqs[R];
    unsigned flmin[R];
#pragma unroll
    for (int r = 0; r < R; r++) {
        int row = s0 + tid + r * T;
        const float* p = src + ((size_t)b * Nn + row) * 3;
        float x = p[0], y = p[1], z = p[2];
        sxn[r] = -2.0f * x; syn[r] = -2.0f * y; szn[r] = -2.0f * z;
        sqs[r] = fmaf(x, x, fmaf(y, y, z * z));
        flmin[r] = 0x7f800000u;  // +INF bits; min over j of d2 bits (s32 order)
    }
    __syncthreads();

    // Column-partial output slice for this warp
    float* colp = g_colp + ((size_t)(by * NWARP + w)) * BN + b * Mn + t0;

    // Main sweep: 2 columns per step. All min-reductions in s32 domain
    // (raw bits of nonneg d2) using 3-input vmin.
#pragma unroll 1
    for (int g = 0; g < TC / 32; g++) {
        unsigned cg = 0x7f800000u;
#pragma unroll
        for (int jc = 0; jc < 32; jc += 2) {
            float4 ta = tsh[g * 32 + jc];      // broadcast LDS.128
            float4 tb = tsh[g * 32 + jc + 1];  // broadcast LDS.128
            unsigned fa[R], fb[R];
#pragma unroll
            for (int r = 0; r < R; r++) {
                float ea = fmaf(sxn[r], ta.x, ta.w);
                ea = fmaf(syn[r], ta.y, ea);
                ea = fmaf(szn[r], ta.z, ea);               // |ta|^2 - 2c_a
                float eb = fmaf(sxn[r], tb.x, tb.w);
                eb = fmaf(syn[r], tb.y, eb);
                eb = fmaf(szn[r], tb.z, eb);               // |tb|^2 - 2c_b
                fa[r] = __float_as_uint(fma1(ea, sqs[r])); // d2_a bits
                fb[r] = __float_as_uint(fma1(eb, sqs[r])); // d2_b bits
                flmin[r] = min3u(flmin[r], fa[r], fb[r]);  // row-acc: 1 vmin3
            }
            // Per-column tree over 8 rows: 4 inst each (3x min3 + combine)
            unsigned ka = min3u(min3u(fa[0], fa[1], fa[2]),
                                min3u(fa[3], fa[4], fa[5]),
                                min(fa[6], fa[7]));
            unsigned kb = min3u(min3u(fb[0], fb[1], fb[2]),
                                min3u(fb[3], fb[4], fb[5]),
                                min(fb[6], fb[7]));
            ka = redux_min(ka);
            kb = redux_min(kb);
            cg = (lane == jc)     ? ka : cg;  // ALU capture, no smem
            cg = (lane == jc + 1) ? kb : cg;
        }
        colp[g * 32 + lane] = __uint_as_float(cg);  // coalesced per-warp STG
    }

    // Row partials: flmin holds min d2 bits over this chunk (coalesced)
#pragma unroll
    for (int r = 0; r < R; r++)
        g_rowp[bx * BN + b * Nn + s0 + tid + r * T] = __uint_as_float(flmin[r]);
}

// Stage 2: blocks 0..127 reduce rows, 128..255 reduce cols (32 slices each).
__global__ void reduce_partials() {
    __shared__ float sh[256];
    const int tid = threadIdx.x;
    const int blk = blockIdx.x;
    const float* base = (blk < 128) ? g_rowp : g_colp;
    const int gi = (blk & 127) * 256 + tid;  // one row/col per thread
    float m = base[gi];
#pragma unroll
    for (int k = 1; k < 32; k++) m = fminf(m, base[k * BN + gi]);
    sh[tid] = m;
    __syncthreads();
#pragma unroll
    for (int st = 128; st > 0; st >>= 1) {
        if (tid < st) sh[tid] += sh[tid + st];
        __syncthreads();
    }
    if (tid == 0) g_bsum[blk] = sh[0];
}

__global__ void final_sum(float* out) {
    __shared__ float sh[256];
    int tid = threadIdx.x;
    sh[tid] = g_bsum[tid];
    __syncthreads();
#pragma unroll
    for (int st = 128; st > 0; st >>= 1) {
        if (tid < st) sh[tid] += sh[tid + st];
        __syncthreads();
    }
    if (tid == 0)
        out[0] = sh[0] / (float)(Bn * Nn);  // (sum_rows + sum_cols) / (B*G)
}

extern "C" void kernel_launch(void* const* d_in, const int* in_sizes, int n_in,
                              void* d_out, int out_size) {
    const float* src = (const float*)d_in[0];  // (4, 8192, 3) fp32
    const float* tgt = (const float*)d_in[1];  // (4, 8192, 3) fp32
    float* out = (float*)d_out;

    dim3 grid(NBX, NBY, Bn);  // (32, 8, 4) = 1024 blocks
    chamfer_main<<<grid, T>>>(src, tgt);
    reduce_partials<<<256, 256>>>();
    final_sum<<<1, 256>>>(out);
}